// round 1
// baseline (speedup 1.0000x reference)
#include <cuda_runtime.h>
#include <math.h>

#define D_MODEL 1024
#define NHEAD   16
#define DK      64
#define SEQ     2048
#define BATCH   2
#define MROWS   (BATCH*SEQ)   // 4096

// Scratch buffers (static device globals — no allocation at runtime)
__device__ float g_Q[MROWS * D_MODEL];
__device__ float g_K[MROWS * D_MODEL];
__device__ float g_V[MROWS * D_MODEL];
__device__ float g_A[MROWS * D_MODEL];

// ---------------------------------------------------------------------------
// SGEMM: C[M,N] = A[M,K] @ B[K,N] + bias[N]
// 128x128 block tile, BK=8, 256 threads, 8x8 per-thread tile.
// All dims divisible by tiles (M=4096, N=1024, K=1024) -> no bounds checks.
// ---------------------------------------------------------------------------
__global__ __launch_bounds__(256) void sgemm_bias(
    const float* __restrict__ A, const float* __restrict__ B,
    const float* __restrict__ bias, float* __restrict__ C,
    int M, int N, int K)
{
    const int BM = 128, BN = 128, BK = 8;
    __shared__ float As[BK][BM];
    __shared__ float Bs[BK][BN];

    int tid = threadIdx.x;
    int tx = tid & 15;          // 0..15 (col group)
    int ty = tid >> 4;          // 0..15 (row group)
    int rowBase = blockIdx.y * BM;
    int colBase = blockIdx.x * BN;

    // A tile load mapping: 128 rows x 8 k, one float4 per thread
    int aRow = tid >> 1;            // 0..127
    int aCol = (tid & 1) * 4;       // 0 or 4
    // B tile load mapping: 8 k-rows x 128 cols, one float4 per thread
    int bRow = tid >> 5;            // 0..7
    int bCol = (tid & 31) * 4;      // 0..124

    float acc[8][8];
    #pragma unroll
    for (int i = 0; i < 8; i++)
        #pragma unroll
        for (int j = 0; j < 8; j++) acc[i][j] = 0.f;

    for (int k0 = 0; k0 < K; k0 += BK) {
        float4 a = *(const float4*)&A[(size_t)(rowBase + aRow) * K + k0 + aCol];
        As[aCol + 0][aRow] = a.x;
        As[aCol + 1][aRow] = a.y;
        As[aCol + 2][aRow] = a.z;
        As[aCol + 3][aRow] = a.w;
        *(float4*)&Bs[bRow][bCol] =
            *(const float4*)&B[(size_t)(k0 + bRow) * N + colBase + bCol];
        __syncthreads();

        #pragma unroll
        for (int k = 0; k < BK; k++) {
            float ra[8], rb[8];
            *(float4*)&ra[0] = *(float4*)&As[k][ty * 8];
            *(float4*)&ra[4] = *(float4*)&As[k][ty * 8 + 4];
            *(float4*)&rb[0] = *(float4*)&Bs[k][tx * 8];
            *(float4*)&rb[4] = *(float4*)&Bs[k][tx * 8 + 4];
            #pragma unroll
            for (int i = 0; i < 8; i++)
                #pragma unroll
                for (int j = 0; j < 8; j++)
                    acc[i][j] = fmaf(ra[i], rb[j], acc[i][j]);
        }
        __syncthreads();
    }

    #pragma unroll
    for (int i = 0; i < 8; i++) {
        int r = rowBase + ty * 8 + i;
        #pragma unroll
        for (int j = 0; j < 8; j += 4) {
            int c = colBase + tx * 8 + j;
            float4 o;
            o.x = acc[i][j + 0] + bias[c + 0];
            o.y = acc[i][j + 1] + bias[c + 1];
            o.z = acc[i][j + 2] + bias[c + 2];
            o.w = acc[i][j + 3] + bias[c + 3];
            *(float4*)&C[(size_t)r * N + c] = o;
        }
    }
}

// ---------------------------------------------------------------------------
// RoPE applied in-place to Q and K. One thread per (b,s,h,pair).
// Layout: row (b*SEQ+s), col h*64 + 2*i / 2*i+1, interleaved pairs.
// ---------------------------------------------------------------------------
__global__ void rope_kernel(float* __restrict__ Q, float* __restrict__ K)
{
    int idx = blockIdx.x * blockDim.x + threadIdx.x;
    // bits: i[0:5) h[5:9) s[9:20) b[20]
    int i = idx & 31;
    int h = (idx >> 5) & 15;
    int s = (idx >> 9) & (SEQ - 1);
    int b = idx >> 20;

    float e   = (float)(2 * i) / 64.0f;
    float inv = powf(10000.0f, -e);
    float ang = (float)s * inv;
    float c, sn;
    __sincosf(ang, &sn, &c);
    // use accurate versions for safety
    c  = cosf(ang);
    sn = sinf(ang);

    size_t base = (size_t)(b * SEQ + s) * D_MODEL + h * DK + 2 * i;
    float qe = Q[base], qo = Q[base + 1];
    Q[base]     = qe * c - qo * sn;
    Q[base + 1] = qe * sn + qo * c;
    float ke = K[base], ko = K[base + 1];
    K[base]     = ke * c - ko * sn;
    K[base + 1] = ke * sn + ko * c;
}

// ---------------------------------------------------------------------------
// Flash attention (causal, fp32, online softmax).
// Block: one (b,h, 64-query tile). 256 threads (16x16).
// Key tiles of 32; only tiles with kpos <= last query position are visited.
// ---------------------------------------------------------------------------
#define BQ  64
#define BKT 32
__global__ __launch_bounds__(256) void flash_kernel(
    const float* __restrict__ Q, const float* __restrict__ K,
    const float* __restrict__ V, float* __restrict__ O)
{
    __shared__ float Qs[BQ][DK + 1];
    __shared__ float Ks[BKT][DK + 1];
    __shared__ float Vs[BKT][DK + 1];
    __shared__ float Ss[BQ][BKT + 1];
    __shared__ float m_s[BQ], l_s[BQ], corr_s[BQ];

    int tid = threadIdx.x;
    int tx = tid & 15;      // 0..15
    int ty = tid >> 4;      // 0..15
    int qt = blockIdx.x;    // query tile (0..31)
    int bh = blockIdx.y;    // 0..31
    int b = bh / NHEAD, h = bh % NHEAD;
    int colOff = h * DK;
    const float scale = 0.125f;     // 1/sqrt(64)

    // load Q tile (64x64)
    for (int e = tid; e < BQ * (DK / 4); e += 256) {
        int r  = e / (DK / 4);
        int c4 = (e % (DK / 4)) * 4;
        float4 v = *(const float4*)&Q[(size_t)(b * SEQ + qt * BQ + r) * D_MODEL + colOff + c4];
        Qs[r][c4] = v.x; Qs[r][c4 + 1] = v.y; Qs[r][c4 + 2] = v.z; Qs[r][c4 + 3] = v.w;
    }
    if (tid < BQ) { m_s[tid] = -1e30f; l_s[tid] = 0.f; }

    float acc[4][4];
    #pragma unroll
    for (int i = 0; i < 4; i++)
        #pragma unroll
        for (int j = 0; j < 4; j++) acc[i][j] = 0.f;

    int nkt = ((qt + 1) * BQ) / BKT;     // causal: tiles fully/partially <= last q

    for (int kt = 0; kt < nkt; kt++) {
        // load K,V tiles (32x64 each)
        for (int e = tid; e < BKT * (DK / 4); e += 256) {
            int r  = e / (DK / 4);
            int c4 = (e % (DK / 4)) * 4;
            size_t g = (size_t)(b * SEQ + kt * BKT + r) * D_MODEL + colOff + c4;
            float4 kv = *(const float4*)&K[g];
            Ks[r][c4] = kv.x; Ks[r][c4 + 1] = kv.y; Ks[r][c4 + 2] = kv.z; Ks[r][c4 + 3] = kv.w;
            float4 vv = *(const float4*)&V[g];
            Vs[r][c4] = vv.x; Vs[r][c4 + 1] = vv.y; Vs[r][c4 + 2] = vv.z; Vs[r][c4 + 3] = vv.w;
        }
        __syncthreads();

        // scores: thread computes rows ty*4..+3, cols tx*2..+1
        float sc[4][2];
        #pragma unroll
        for (int i = 0; i < 4; i++) { sc[i][0] = 0.f; sc[i][1] = 0.f; }
        #pragma unroll 8
        for (int k = 0; k < DK; k++) {
            float kv0 = Ks[tx * 2][k];
            float kv1 = Ks[tx * 2 + 1][k];
            #pragma unroll
            for (int i = 0; i < 4; i++) {
                float qv = Qs[ty * 4 + i][k];
                sc[i][0] = fmaf(qv, kv0, sc[i][0]);
                sc[i][1] = fmaf(qv, kv1, sc[i][1]);
            }
        }
        int qbase = qt * BQ, kbase = kt * BKT;
        #pragma unroll
        for (int i = 0; i < 4; i++) {
            int qpos = qbase + ty * 4 + i;
            #pragma unroll
            for (int j = 0; j < 2; j++) {
                int kpos = kbase + tx * 2 + j;
                float s = sc[i][j] * scale;
                if (kpos > qpos) s = -1e9f;
                Ss[ty * 4 + i][tx * 2 + j] = s;
            }
        }
        __syncthreads();

        // per-row online softmax update (first 64 threads)
        if (tid < BQ) {
            int r = tid;
            float mo = m_s[r];
            float mx = mo;
            #pragma unroll 8
            for (int j = 0; j < BKT; j++) mx = fmaxf(mx, Ss[r][j]);
            float c = __expf(mo - mx);
            float sum = 0.f;
            #pragma unroll 8
            for (int j = 0; j < BKT; j++) {
                float p = __expf(Ss[r][j] - mx);
                Ss[r][j] = p;
                sum += p;
            }
            m_s[r] = mx;
            l_s[r] = l_s[r] * c + sum;
            corr_s[r] = c;
        }
        __syncthreads();

        // O update: acc = acc*corr + P(64x32) @ V(32x64); thread tile 4x4
        #pragma unroll
        for (int i = 0; i < 4; i++) {
            float c = corr_s[ty * 4 + i];
            #pragma unroll
            for (int j = 0; j < 4; j++) acc[i][j] *= c;
        }
        #pragma unroll 4
        for (int kk = 0; kk < BKT; kk++) {
            float vv[4];
            #pragma unroll
            for (int j = 0; j < 4; j++) vv[j] = Vs[kk][tx * 4 + j];
            #pragma unroll
            for (int i = 0; i < 4; i++) {
                float p = Ss[ty * 4 + i][kk];
                #pragma unroll
                for (int j = 0; j < 4; j++)
                    acc[i][j] = fmaf(p, vv[j], acc[i][j]);
            }
        }
        __syncthreads();
    }

    // finalize: divide by l, write out (B,S,H,dk) layout
    #pragma unroll
    for (int i = 0; i < 4; i++) {
        int r = ty * 4 + i;
        float inv_l = 1.0f / l_s[r];
        size_t grow = (size_t)(b * SEQ + qt * BQ + r) * D_MODEL + colOff;
        #pragma unroll
        for (int j = 0; j < 4; j++)
            O[grow + tx * 4 + j] = acc[i][j] * inv_l;
    }
}

// ---------------------------------------------------------------------------
extern "C" void kernel_launch(void* const* d_in, const int* in_sizes, int n_in,
                              void* d_out, int out_size)
{
    const float* x  = (const float*)d_in[0];
    const float* Wq = (const float*)d_in[1];
    const float* bq = (const float*)d_in[2];
    const float* Wk = (const float*)d_in[3];
    const float* bk = (const float*)d_in[4];
    const float* Wv = (const float*)d_in[5];
    const float* bv = (const float*)d_in[6];
    const float* Wo = (const float*)d_in[7];
    const float* bo = (const float*)d_in[8];
    float* out = (float*)d_out;

    float *Qp, *Kp, *Vp, *Ap;
    cudaGetSymbolAddress((void**)&Qp, g_Q);
    cudaGetSymbolAddress((void**)&Kp, g_K);
    cudaGetSymbolAddress((void**)&Vp, g_V);
    cudaGetSymbolAddress((void**)&Ap, g_A);

    dim3 gemmGrid(D_MODEL / 128, MROWS / 128);   // (8, 32)
    sgemm_bias<<<gemmGrid, 256>>>(x, Wq, bq, Qp, MROWS, D_MODEL, D_MODEL);
    sgemm_bias<<<gemmGrid, 256>>>(x, Wk, bk, Kp, MROWS, D_MODEL, D_MODEL);
    sgemm_bias<<<gemmGrid, 256>>>(x, Wv, bv, Vp, MROWS, D_MODEL, D_MODEL);

    int ropeThreads = BATCH * SEQ * NHEAD * (DK / 2);   // 2M
    rope_kernel<<<ropeThreads / 256, 256>>>(Qp, Kp);

    dim3 flashGrid(SEQ / BQ, BATCH * NHEAD);     // (32, 32)
    flash_kernel<<<flashGrid, 256>>>(Qp, Kp, Vp, Ap);

    sgemm_bias<<<gemmGrid, 256>>>(Ap, Wo, bo, out, MROWS, D_MODEL, D_MODEL);
}

// round 8
// speedup vs baseline: 2.8402x; 2.8402x over previous
#include <cuda_runtime.h>
#include <cuda_bf16.h>
#include <stdint.h>
#include <math.h>

#define D_MODEL 1024
#define NHEAD   16
#define DK      64
#define SEQ     2048
#define BATCH   2
#define MROWS   (BATCH*SEQ)   // 4096

// Scratch (static device globals — no runtime allocation)
__device__ float g_A[MROWS * D_MODEL];                    // attention output (fp32)
__device__ __nv_bfloat16 g_Qh[MROWS * D_MODEL], g_Ql[MROWS * D_MODEL];
__device__ __nv_bfloat16 g_Kh[MROWS * D_MODEL], g_Kl[MROWS * D_MODEL];
__device__ __nv_bfloat16 g_Vh[MROWS * D_MODEL], g_Vl[MROWS * D_MODEL];
__device__ float2 g_ropeTab[SEQ * 32];                    // (cos, sin) per (s, i)

// ---------------------------------------------------------------------------
// Helpers: ldmatrix / mma / split-pack
// ---------------------------------------------------------------------------
__device__ __forceinline__ uint32_t smem_u32(const void* p) {
    return (uint32_t)__cvta_generic_to_shared(p);
}
__device__ __forceinline__ void ldm_x4(uint32_t r[4], uint32_t addr) {
    asm volatile("ldmatrix.sync.aligned.m8n8.x4.shared.b16 {%0,%1,%2,%3}, [%4];"
                 : "=r"(r[0]), "=r"(r[1]), "=r"(r[2]), "=r"(r[3]) : "r"(addr));
}
__device__ __forceinline__ void ldm_x4_t(uint32_t r[4], uint32_t addr) {
    asm volatile("ldmatrix.sync.aligned.m8n8.x4.trans.shared.b16 {%0,%1,%2,%3}, [%4];"
                 : "=r"(r[0]), "=r"(r[1]), "=r"(r[2]), "=r"(r[3]) : "r"(addr));
}
__device__ __forceinline__ void ldm_x2_t(uint32_t r[2], uint32_t addr) {
    asm volatile("ldmatrix.sync.aligned.m8n8.x2.trans.shared.b16 {%0,%1}, [%2];"
                 : "=r"(r[0]), "=r"(r[1]) : "r"(addr));
}
__device__ __forceinline__ void mma_bf16(float c[4], const uint32_t a[4], const uint32_t b[2]) {
    asm volatile(
        "mma.sync.aligned.m16n8k16.row.col.f32.bf16.bf16.f32 "
        "{%0,%1,%2,%3}, {%4,%5,%6,%7}, {%8,%9}, {%0,%1,%2,%3};"
        : "+f"(c[0]), "+f"(c[1]), "+f"(c[2]), "+f"(c[3])
        : "r"(a[0]), "r"(a[1]), "r"(a[2]), "r"(a[3]), "r"(b[0]), "r"(b[1]));
}
__device__ __forceinline__ void f32split(float x, __nv_bfloat16& h, __nv_bfloat16& l) {
    h = __float2bfloat16(x);
    l = __float2bfloat16(x - __bfloat162float(h));
}
__device__ __forceinline__ uint32_t packb2(__nv_bfloat16 a, __nv_bfloat16 b) {
    __nv_bfloat162 t(a, b);
    return *(uint32_t*)&t;
}
__device__ __forceinline__ void packsplit(float a, float b, uint32_t& hi, uint32_t& lo) {
    __nv_bfloat16 ha, la, hb, lb;
    f32split(a, ha, la); f32split(b, hb, lb);
    hi = packb2(ha, hb); lo = packb2(la, lb);
}

// ---------------------------------------------------------------------------
// RoPE table: (cos, sin) for s in [0,2048), i in [0,32)
// ---------------------------------------------------------------------------
__global__ void rope_table_kernel(float2* tab) {
    int idx = blockIdx.x * 256 + threadIdx.x;     // 65536 total
    int s = idx >> 5, i = idx & 31;
    float inv = powf(10000.0f, -(float)(2 * i) / 64.0f);
    float ang = (float)s * inv;
    tab[idx] = make_float2(cosf(ang), sinf(ang));
}

// ---------------------------------------------------------------------------
// Tensor-core GEMM, fp32 in, bf16x3 (hi/lo split) compute, modes:
//   mode 0: C = A@B + bias, fp32 out
//   mode 1: rope(A@B + bias) * 0.125 -> split -> (Ch, Cl)   [Q]
//   mode 2: rope(A@B + bias)         -> split -> (Ch, Cl)   [K]
//   mode 3: (A@B + bias)             -> split -> (Ch, Cl)   [V]
// Block 128x128x32, 256 threads, warp tile 64x32.
// ---------------------------------------------------------------------------
#define GBM 128
#define GBN 128
#define GBK 32
#define APAD 8
#define BPAD 8

__global__ __launch_bounds__(256) void gemm_bf16x3(
    const float* __restrict__ A, const float* __restrict__ B,
    const float* __restrict__ bias, float* __restrict__ C,
    __nv_bfloat16* __restrict__ Ch, __nv_bfloat16* __restrict__ Cl,
    const float2* __restrict__ ropeTab, int mode,
    int M, int N, int K)
{
    __shared__ __align__(16) __nv_bfloat16 Ah[GBM][GBK + APAD];
    __shared__ __align__(16) __nv_bfloat16 Al[GBM][GBK + APAD];
    __shared__ __align__(16) __nv_bfloat16 Bh[GBK][GBN + BPAD];
    __shared__ __align__(16) __nv_bfloat16 Bl[GBK][GBN + BPAD];

    const int tid  = threadIdx.x;
    const int lane = tid & 31;
    const int warp = tid >> 5;
    const int wm   = warp & 1;
    const int wn   = warp >> 1;
    const int rowBase = blockIdx.y * GBM;
    const int colBase = blockIdx.x * GBN;

    float acc[4][4][4];
    #pragma unroll
    for (int i = 0; i < 4; i++)
        #pragma unroll
        for (int j = 0; j < 4; j++)
            #pragma unroll
            for (int r = 0; r < 4; r++) acc[i][j][r] = 0.f;

    for (int k0 = 0; k0 < K; k0 += GBK) {
        #pragma unroll
        for (int l = 0; l < 4; l++) {
            int e  = tid + l * 256;
            int r  = e >> 3;
            int c4 = (e & 7) << 2;
            float4 v = *(const float4*)&A[(size_t)(rowBase + r) * K + k0 + c4];
            __nv_bfloat16 h, lo;
            f32split(v.x, h, lo); Ah[r][c4 + 0] = h; Al[r][c4 + 0] = lo;
            f32split(v.y, h, lo); Ah[r][c4 + 1] = h; Al[r][c4 + 1] = lo;
            f32split(v.z, h, lo); Ah[r][c4 + 2] = h; Al[r][c4 + 2] = lo;
            f32split(v.w, h, lo); Ah[r][c4 + 3] = h; Al[r][c4 + 3] = lo;
        }
        #pragma unroll
        for (int l = 0; l < 4; l++) {
            int e  = tid + l * 256;
            int r  = e >> 5;
            int c4 = (e & 31) << 2;
            float4 v = *(const float4*)&B[(size_t)(k0 + r) * N + colBase + c4];
            __nv_bfloat16 h, lo;
            f32split(v.x, h, lo); Bh[r][c4 + 0] = h; Bl[r][c4 + 0] = lo;
            f32split(v.y, h, lo); Bh[r][c4 + 1] = h; Bl[r][c4 + 1] = lo;
            f32split(v.z, h, lo); Bh[r][c4 + 2] = h; Bl[r][c4 + 2] = lo;
            f32split(v.w, h, lo); Bh[r][c4 + 3] = h; Bl[r][c4 + 3] = lo;
        }
        __syncthreads();

        #pragma unroll
        for (int ks = 0; ks < GBK; ks += 16) {
            uint32_t ah[4][4], al[4][4];
            #pragma unroll
            for (int am = 0; am < 4; am++) {
                int row = wm * 64 + am * 16 + (lane & 15);
                int col = ks + ((lane >> 4) << 3);
                ldm_x4(ah[am], smem_u32(&Ah[row][col]));
                ldm_x4(al[am], smem_u32(&Al[row][col]));
            }
            #pragma unroll
            for (int an = 0; an < 4; an++) {
                int br = ks + (lane & 15);
                int bc = wn * 32 + an * 8;
                uint32_t bh[2], bl[2];
                ldm_x2_t(bh, smem_u32(&Bh[br][bc]));
                ldm_x2_t(bl, smem_u32(&Bl[br][bc]));
                #pragma unroll
                for (int am = 0; am < 4; am++) {
                    mma_bf16(acc[am][an], ah[am], bh);
                    mma_bf16(acc[am][an], ah[am], bl);
                    mma_bf16(acc[am][an], al[am], bh);
                }
            }
        }
        __syncthreads();
    }

    // Epilogue. Fragment: c0:(r,c) c1:(r,c+1) c2:(r+8,c) c3:(r+8,c+1), c even.
    #pragma unroll
    for (int am = 0; am < 4; am++) {
        #pragma unroll
        for (int an = 0; an < 4; an++) {
            int r0 = rowBase + wm * 64 + am * 16 + (lane >> 2);
            int c0 = colBase + wn * 32 + an * 8 + ((lane & 3) << 1);
            float b0 = bias[c0], b1 = bias[c0 + 1];
            float v00 = acc[am][an][0] + b0, v01 = acc[am][an][1] + b1;
            float v10 = acc[am][an][2] + b0, v11 = acc[am][an][3] + b1;
            if (mode == 0) {
                C[(size_t)r0 * N + c0]           = v00;
                C[(size_t)r0 * N + c0 + 1]       = v01;
                C[(size_t)(r0 + 8) * N + c0]     = v10;
                C[(size_t)(r0 + 8) * N + c0 + 1] = v11;
            } else {
                if (mode != 3) {   // rope for Q, K
                    int i  = (c0 & 63) >> 1;
                    int s0 = r0 & (SEQ - 1);
                    float2 cs0 = ropeTab[s0 * 32 + i];
                    float2 cs1 = ropeTab[(s0 + 8) * 32 + i];
                    float t;
                    t = v00 * cs0.x - v01 * cs0.y; v01 = v00 * cs0.y + v01 * cs0.x; v00 = t;
                    t = v10 * cs1.x - v11 * cs1.y; v11 = v10 * cs1.y + v11 * cs1.x; v10 = t;
                }
                if (mode == 1) { v00 *= 0.125f; v01 *= 0.125f; v10 *= 0.125f; v11 *= 0.125f; }
                uint32_t h0, l0, h1, l1;
                packsplit(v00, v01, h0, l0);
                packsplit(v10, v11, h1, l1);
                size_t i0 = (size_t)r0 * N + c0;
                size_t i1 = (size_t)(r0 + 8) * N + c0;
                *(uint32_t*)&Ch[i0] = h0; *(uint32_t*)&Cl[i0] = l0;
                *(uint32_t*)&Ch[i1] = h1; *(uint32_t*)&Cl[i1] = l1;
            }
        }
    }
}

// ---------------------------------------------------------------------------
// Tensor-core flash attention (causal). bf16 hi/lo inputs, fp32 softmax/accum.
// Block: (qtile 64 rows, one (b,h)). 128 threads = 4 warps, 16 q rows/warp.
// K tiles of 64. S = Qh*Kh + Qh*Kl + Ql*Kh; O += Ph*Vh + Pl*Vh + Ph*Vl.
// Q pre-scaled by 1/8 (folded in projection epilogue).
// ---------------------------------------------------------------------------
__global__ __launch_bounds__(128) void flash_mma(
    const __nv_bfloat16* __restrict__ Qh, const __nv_bfloat16* __restrict__ Ql,
    const __nv_bfloat16* __restrict__ Kh, const __nv_bfloat16* __restrict__ Kl,
    const __nv_bfloat16* __restrict__ Vh, const __nv_bfloat16* __restrict__ Vl,
    float* __restrict__ O)
{
    __shared__ __align__(16) __nv_bfloat16 sKh[64][72];
    __shared__ __align__(16) __nv_bfloat16 sKl[64][72];
    __shared__ __align__(16) __nv_bfloat16 sVh[64][72];
    __shared__ __align__(16) __nv_bfloat16 sVl[64][72];

    const int tid  = threadIdx.x;
    const int lane = tid & 31;
    const int warp = tid >> 5;
    const int qt = blockIdx.x;            // 0..31
    const int bh = blockIdx.y;            // 0..31
    const int b = bh >> 4, h = bh & 15;
    const size_t rowBase = (size_t)b * SEQ;
    const int col0 = h * DK;

    // ---- stage Q tile (64 rows x 64 cols = 512 uint4 per buffer) ----
    for (int e = tid; e < 512; e += 128) {
        int r = e >> 3, c8 = (e & 7) * 8;
        size_t g = (rowBase + qt * 64 + r) * D_MODEL + col0 + c8;
        *(uint4*)&sKh[r][c8] = *(const uint4*)&Qh[g];
        *(uint4*)&sKl[r][c8] = *(const uint4*)&Ql[g];
    }
    __syncthreads();
    uint32_t qh[4][4], ql[4][4];
    #pragma unroll
    for (int c = 0; c < 4; c++) {
        int row = warp * 16 + (lane & 15);
        int col = c * 16 + ((lane >> 4) << 3);
        ldm_x4(qh[c], smem_u32(&sKh[row][col]));
        ldm_x4(ql[c], smem_u32(&sKl[row][col]));
    }
    __syncthreads();

    float m0 = -1e30f, m1 = -1e30f, l0 = 0.f, l1 = 0.f;
    float o[8][4];
    #pragma unroll
    for (int d = 0; d < 8; d++)
        #pragma unroll
        for (int j = 0; j < 4; j++) o[d][j] = 0.f;

    for (int kt = 0; kt <= qt; kt++) {
        // ---- load K/V tiles (full 64x64) ----
        for (int e = tid; e < 512; e += 128) {
            int r = e >> 3, c8 = (e & 7) * 8;
            size_t g = (rowBase + kt * 64 + r) * D_MODEL + col0 + c8;
            *(uint4*)&sKh[r][c8] = *(const uint4*)&Kh[g];
            *(uint4*)&sKl[r][c8] = *(const uint4*)&Kl[g];
            *(uint4*)&sVh[r][c8] = *(const uint4*)&Vh[g];
            *(uint4*)&sVl[r][c8] = *(const uint4*)&Vl[g];
        }
        __syncthreads();

        // ---- S = Q K^T (16 x 64 per warp), 8 n-tiles ----
        float s[8][4];
        #pragma unroll
        for (int nt = 0; nt < 8; nt++)
            #pragma unroll
            for (int j = 0; j < 4; j++) s[nt][j] = 0.f;

        #pragma unroll
        for (int ntp = 0; ntp < 4; ntp++) {       // n-tile pairs (16 keys)
            #pragma unroll
            for (int c = 0; c < 4; c++) {         // dk chunks of 16
                int row = ntp * 16 + ((lane >> 4) & 1) * 8 + (lane & 7);
                int col = c * 16 + ((lane >> 3) & 1) * 8;
                uint32_t kh4[4], kl4[4];
                ldm_x4(kh4, smem_u32(&sKh[row][col]));
                ldm_x4(kl4, smem_u32(&sKl[row][col]));
                mma_bf16(s[2 * ntp],     qh[c], &kh4[0]);
                mma_bf16(s[2 * ntp],     qh[c], &kl4[0]);
                mma_bf16(s[2 * ntp],     ql[c], &kh4[0]);
                mma_bf16(s[2 * ntp + 1], qh[c], &kh4[2]);
                mma_bf16(s[2 * ntp + 1], qh[c], &kl4[2]);
                mma_bf16(s[2 * ntp + 1], ql[c], &kh4[2]);
            }
        }

        // ---- causal mask on diagonal tile ----
        if (kt == qt) {
            int qrow = warp * 16 + (lane >> 2);
            int kcol = (lane & 3) * 2;
            #pragma unroll
            for (int nt = 0; nt < 8; nt++) {
                #pragma unroll
                for (int j = 0; j < 4; j++) {
                    int kpos = nt * 8 + kcol + (j & 1);
                    int qpos = qrow + ((j >> 1) << 3);
                    if (kpos > qpos) s[nt][j] = -1e9f;
                }
            }
        }

        // ---- online softmax ----
        float mx0 = -1e30f, mx1 = -1e30f;
        #pragma unroll
        for (int nt = 0; nt < 8; nt++) {
            mx0 = fmaxf(mx0, fmaxf(s[nt][0], s[nt][1]));
            mx1 = fmaxf(mx1, fmaxf(s[nt][2], s[nt][3]));
        }
        mx0 = fmaxf(mx0, __shfl_xor_sync(0xffffffff, mx0, 1));
        mx0 = fmaxf(mx0, __shfl_xor_sync(0xffffffff, mx0, 2));
        mx1 = fmaxf(mx1, __shfl_xor_sync(0xffffffff, mx1, 1));
        mx1 = fmaxf(mx1, __shfl_xor_sync(0xffffffff, mx1, 2));
        float mn0 = fmaxf(m0, mx0), mn1 = fmaxf(m1, mx1);
        float cr0 = __expf(m0 - mn0), cr1 = __expf(m1 - mn1);
        float sum0 = 0.f, sum1 = 0.f;
        #pragma unroll
        for (int nt = 0; nt < 8; nt++) {
            s[nt][0] = __expf(s[nt][0] - mn0);
            s[nt][1] = __expf(s[nt][1] - mn0);
            s[nt][2] = __expf(s[nt][2] - mn1);
            s[nt][3] = __expf(s[nt][3] - mn1);
            sum0 += s[nt][0] + s[nt][1];
            sum1 += s[nt][2] + s[nt][3];
        }
        sum0 += __shfl_xor_sync(0xffffffff, sum0, 1);
        sum0 += __shfl_xor_sync(0xffffffff, sum0, 2);
        sum1 += __shfl_xor_sync(0xffffffff, sum1, 1);
        sum1 += __shfl_xor_sync(0xffffffff, sum1, 2);
        m0 = mn0; m1 = mn1;
        l0 = l0 * cr0 + sum0;
        l1 = l1 * cr1 + sum1;
        #pragma unroll
        for (int d = 0; d < 8; d++) {
            o[d][0] *= cr0; o[d][1] *= cr0;
            o[d][2] *= cr1; o[d][3] *= cr1;
        }

        // ---- pack P fragments (hi/lo), A-operand order ----
        uint32_t pah[4][4], pal[4][4];
        #pragma unroll
        for (int c = 0; c < 4; c++) {
            packsplit(s[2*c][0],   s[2*c][1],   pah[c][0], pal[c][0]);
            packsplit(s[2*c][2],   s[2*c][3],   pah[c][1], pal[c][1]);
            packsplit(s[2*c+1][0], s[2*c+1][1], pah[c][2], pal[c][2]);
            packsplit(s[2*c+1][2], s[2*c+1][3], pah[c][3], pal[c][3]);
        }

        // ---- O += P V ----
        #pragma unroll
        for (int dtp = 0; dtp < 4; dtp++) {       // d-tile pairs (16 dk)
            #pragma unroll
            for (int c = 0; c < 4; c++) {         // key chunks of 16
                int row = c * 16 + ((lane >> 3) & 1) * 8 + (lane & 7);
                int col = dtp * 16 + ((lane >> 4) & 1) * 8;
                uint32_t vh4[4], vl4[4];
                ldm_x4_t(vh4, smem_u32(&sVh[row][col]));
                ldm_x4_t(vl4, smem_u32(&sVl[row][col]));
                mma_bf16(o[2 * dtp],     pah[c], &vh4[0]);
                mma_bf16(o[2 * dtp],     pal[c], &vh4[0]);
                mma_bf16(o[2 * dtp],     pah[c], &vl4[0]);
                mma_bf16(o[2 * dtp + 1], pah[c], &vh4[2]);
                mma_bf16(o[2 * dtp + 1], pal[c], &vh4[2]);
                mma_bf16(o[2 * dtp + 1], pah[c], &vl4[2]);
            }
        }
        __syncthreads();
    }

    // ---- finalize ----
    float il0 = 1.0f / l0, il1 = 1.0f / l1;
    size_t gr = rowBase + qt * 64 + warp * 16 + (lane >> 2);
    int gc = col0 + (lane & 3) * 2;
    #pragma unroll
    for (int d = 0; d < 8; d++) {
        float2 a = make_float2(o[d][0] * il0, o[d][1] * il0);
        float2 b2 = make_float2(o[d][2] * il1, o[d][3] * il1);
        *(float2*)&O[gr * D_MODEL + gc + d * 8]       = a;
        *(float2*)&O[(gr + 8) * D_MODEL + gc + d * 8] = b2;
    }
}

// ---------------------------------------------------------------------------
extern "C" void kernel_launch(void* const* d_in, const int* in_sizes, int n_in,
                              void* d_out, int out_size)
{
    const float* x  = (const float*)d_in[0];
    const float* Wq = (const float*)d_in[1];
    const float* bq = (const float*)d_in[2];
    const float* Wk = (const float*)d_in[3];
    const float* bk = (const float*)d_in[4];
    const float* Wv = (const float*)d_in[5];
    const float* bv = (const float*)d_in[6];
    const float* Wo = (const float*)d_in[7];
    const float* bo = (const float*)d_in[8];
    float* out = (float*)d_out;

    float* Ap; float2* ropeP;
    __nv_bfloat16 *Qh, *Ql, *Kh, *Kl, *Vh, *Vl;
    cudaGetSymbolAddress((void**)&Ap, g_A);
    cudaGetSymbolAddress((void**)&ropeP, g_ropeTab);
    cudaGetSymbolAddress((void**)&Qh, g_Qh); cudaGetSymbolAddress((void**)&Ql, g_Ql);
    cudaGetSymbolAddress((void**)&Kh, g_Kh); cudaGetSymbolAddress((void**)&Kl, g_Kl);
    cudaGetSymbolAddress((void**)&Vh, g_Vh); cudaGetSymbolAddress((void**)&Vl, g_Vl);

    rope_table_kernel<<<SEQ * 32 / 256, 256>>>(ropeP);

    dim3 gemmGrid(D_MODEL / GBN, MROWS / GBM);   // (8, 32)
    gemm_bf16x3<<<gemmGrid, 256>>>(x, Wq, bq, nullptr, Qh, Ql, ropeP, 1, MROWS, D_MODEL, D_MODEL);
    gemm_bf16x3<<<gemmGrid, 256>>>(x, Wk, bk, nullptr, Kh, Kl, ropeP, 2, MROWS, D_MODEL, D_MODEL);
    gemm_bf16x3<<<gemmGrid, 256>>>(x, Wv, bv, nullptr, Vh, Vl, ropeP, 3, MROWS, D_MODEL, D_MODEL);

    dim3 flashGrid(SEQ / 64, BATCH * NHEAD);     // (32, 32)
    flash_mma<<<flashGrid, 128>>>(Qh, Ql, Kh, Kl, Vh, Vl, Ap);

    gemm_bf16x3<<<gemmGrid, 256>>>(Ap, Wo, bo, out, nullptr, nullptr, ropeP, 0, MROWS, D_MODEL, D_MODEL);
}

// round 9
// speedup vs baseline: 2.9510x; 1.0390x over previous
#include <cuda_runtime.h>
#include <cuda_bf16.h>
#include <stdint.h>
#include <math.h>

#define D_MODEL 1024
#define NHEAD   16
#define DK      64
#define SEQ     2048
#define BATCH   2
#define MROWS   (BATCH*SEQ)   // 4096

// ---------------- device scratch (no runtime allocation) ----------------
__device__ __nv_bfloat16 g_xh[MROWS * D_MODEL], g_xl[MROWS * D_MODEL];
__device__ __nv_bfloat16 g_Wh[4][D_MODEL * D_MODEL], g_Wl[4][D_MODEL * D_MODEL]; // q,k,v,o
__device__ __nv_bfloat16 g_Qh[MROWS * D_MODEL], g_Ql[MROWS * D_MODEL];
__device__ __nv_bfloat16 g_Kh[MROWS * D_MODEL], g_Kl[MROWS * D_MODEL];
__device__ __nv_bfloat16 g_Vh[MROWS * D_MODEL], g_Vl[MROWS * D_MODEL];
__device__ __nv_bfloat16 g_Ah[MROWS * D_MODEL], g_Al[MROWS * D_MODEL];
__device__ float2 g_ropeTab[SEQ * 32];

// ---------------- helpers ----------------
__device__ __forceinline__ uint32_t smem_u32(const void* p) {
    return (uint32_t)__cvta_generic_to_shared(p);
}
__device__ __forceinline__ void ldm_x4(uint32_t r[4], uint32_t addr) {
    asm volatile("ldmatrix.sync.aligned.m8n8.x4.shared.b16 {%0,%1,%2,%3}, [%4];"
                 : "=r"(r[0]), "=r"(r[1]), "=r"(r[2]), "=r"(r[3]) : "r"(addr));
}
__device__ __forceinline__ void ldm_x4_t(uint32_t r[4], uint32_t addr) {
    asm volatile("ldmatrix.sync.aligned.m8n8.x4.trans.shared.b16 {%0,%1,%2,%3}, [%4];"
                 : "=r"(r[0]), "=r"(r[1]), "=r"(r[2]), "=r"(r[3]) : "r"(addr));
}
__device__ __forceinline__ void ldm_x2_t(uint32_t r[2], uint32_t addr) {
    asm volatile("ldmatrix.sync.aligned.m8n8.x2.trans.shared.b16 {%0,%1}, [%2];"
                 : "=r"(r[0]), "=r"(r[1]) : "r"(addr));
}
__device__ __forceinline__ void mma_bf16(float c[4], const uint32_t a[4], const uint32_t b[2]) {
    asm volatile(
        "mma.sync.aligned.m16n8k16.row.col.f32.bf16.bf16.f32 "
        "{%0,%1,%2,%3}, {%4,%5,%6,%7}, {%8,%9}, {%0,%1,%2,%3};"
        : "+f"(c[0]), "+f"(c[1]), "+f"(c[2]), "+f"(c[3])
        : "r"(a[0]), "r"(a[1]), "r"(a[2]), "r"(a[3]), "r"(b[0]), "r"(b[1]));
}
__device__ __forceinline__ void f32split(float x, __nv_bfloat16& h, __nv_bfloat16& l) {
    h = __float2bfloat16(x);
    l = __float2bfloat16(x - __bfloat162float(h));
}
__device__ __forceinline__ uint32_t packb2(__nv_bfloat16 a, __nv_bfloat16 b) {
    __nv_bfloat162 t(a, b);
    return *(uint32_t*)&t;
}
__device__ __forceinline__ void packsplit(float a, float b, uint32_t& hi, uint32_t& lo) {
    __nv_bfloat16 ha, la, hb, lb;
    f32split(a, ha, la); f32split(b, hb, lb);
    hi = packb2(ha, hb); lo = packb2(la, lb);
}
__device__ __forceinline__ void cp16(uint32_t saddr, const void* gaddr) {
    asm volatile("cp.async.cg.shared.global [%0], [%1], 16;" :: "r"(saddr), "l"(gaddr));
}

// ---------------- prep: fp32 -> bf16 hi/lo split (8 floats/thread) ----------------
__global__ void split_kernel(const float* __restrict__ in,
                             __nv_bfloat16* __restrict__ h,
                             __nv_bfloat16* __restrict__ l, int n8)
{
    int i = blockIdx.x * 256 + threadIdx.x;
    if (i >= n8) return;
    const float4* p = (const float4*)in + (size_t)i * 2;
    float4 a = p[0], b = p[1];
    uint4 oh, ol;
    uint32_t h0, l0;
    packsplit(a.x, a.y, h0, l0); oh.x = h0; ol.x = l0;
    packsplit(a.z, a.w, h0, l0); oh.y = h0; ol.y = l0;
    packsplit(b.x, b.y, h0, l0); oh.z = h0; ol.z = l0;
    packsplit(b.z, b.w, h0, l0); oh.w = h0; ol.w = l0;
    ((uint4*)h)[i] = oh;
    ((uint4*)l)[i] = ol;
}

// ---------------- RoPE table ----------------
__global__ void rope_table_kernel(float2* tab) {
    int idx = blockIdx.x * 256 + threadIdx.x;     // 65536
    int s = idx >> 5, i = idx & 31;
    float inv = powf(10000.0f, -(float)(2 * i) / 64.0f);
    float ang = (float)s * inv;
    tab[idx] = make_float2(cosf(ang), sinf(ang));
}

// ---------------------------------------------------------------------------
// Pipelined bf16x3 GEMM. All operands pre-split bf16. 2-stage cp.async.
// Block 128x128x32, 256 threads, warp tile 64x32.
// qkv=1: grid.z selects {Q:rope+scale, K:rope, V:plain} -> split outputs.
// qkv=0: slot0, fp32 output Cf (+bias).
// ---------------------------------------------------------------------------
#define ASTRIDE 40      // halfs per A row (32 + 8 pad); 80B = 5x16B (odd) -> conflict-free
#define BSTRIDE 136     // halfs per B row (128 + 8 pad); 272B = 17x16B (odd)
#define A_HALFS (128 * ASTRIDE)
#define B_HALFS (32 * BSTRIDE)
#define STAGE_HALFS (2 * A_HALFS + 2 * B_HALFS)   // 18944 halfs = 37888 B
#define SMEM_BYTES (2 * STAGE_HALFS * 2)          // 75776 B

__device__ __forceinline__ void stage_tiles(
    __nv_bfloat16* sb,
    const __nv_bfloat16* __restrict__ Agh, const __nv_bfloat16* __restrict__ Agl,
    const __nv_bfloat16* __restrict__ Bgh, const __nv_bfloat16* __restrict__ Bgl,
    int rowBase, int colBase, int t, int tid)
{
    __nv_bfloat16* sAh = sb;
    __nv_bfloat16* sAl = sb + A_HALFS;
    __nv_bfloat16* sBh = sb + 2 * A_HALFS;
    __nv_bfloat16* sBl = sb + 2 * A_HALFS + B_HALFS;
    #pragma unroll
    for (int g = 0; g < 2; g++) {
        int e  = tid + g * 256;
        int r  = e >> 2, c8 = (e & 3) * 8;           // A: 128 rows x 32 cols
        size_t ga = (size_t)(rowBase + r) * D_MODEL + t * 32 + c8;
        cp16(smem_u32(sAh + r * ASTRIDE + c8), Agh + ga);
        cp16(smem_u32(sAl + r * ASTRIDE + c8), Agl + ga);
        int rb = e >> 4, cb8 = (e & 15) * 8;         // B: 32 rows x 128 cols
        size_t gb = (size_t)(t * 32 + rb) * D_MODEL + colBase + cb8;
        cp16(smem_u32(sBh + rb * BSTRIDE + cb8), Bgh + gb);
        cp16(smem_u32(sBl + rb * BSTRIDE + cb8), Bgl + gb);
    }
}

__global__ __launch_bounds__(256) void gemm_pipe(
    const __nv_bfloat16* __restrict__ Agh, const __nv_bfloat16* __restrict__ Agl,
    const __nv_bfloat16* __restrict__ B0h, const __nv_bfloat16* __restrict__ B0l, const float* __restrict__ bias0,
    const __nv_bfloat16* __restrict__ B1h, const __nv_bfloat16* __restrict__ B1l, const float* __restrict__ bias1,
    const __nv_bfloat16* __restrict__ B2h, const __nv_bfloat16* __restrict__ B2l, const float* __restrict__ bias2,
    __nv_bfloat16* __restrict__ C0h, __nv_bfloat16* __restrict__ C0l,
    __nv_bfloat16* __restrict__ C1h, __nv_bfloat16* __restrict__ C1l,
    __nv_bfloat16* __restrict__ C2h, __nv_bfloat16* __restrict__ C2l,
    float* __restrict__ Cf,
    const float2* __restrict__ ropeTab, int qkv)
{
    extern __shared__ __align__(16) __nv_bfloat16 sm[];
    const int N = D_MODEL;
    const int tid  = threadIdx.x;
    const int lane = tid & 31;
    const int warp = tid >> 5;
    const int wm   = warp & 1;
    const int wn   = warp >> 1;
    const int rowBase = blockIdx.y * 128;
    const int colBase = blockIdx.x * 128;

    const __nv_bfloat16 *Bgh, *Bgl;
    const float* bias;
    __nv_bfloat16 *Ch = nullptr, *Cl = nullptr;
    int mode;
    if (qkv) {
        int z = blockIdx.z;
        if (z == 0)      { Bgh = B0h; Bgl = B0l; bias = bias0; Ch = C0h; Cl = C0l; mode = 1; }
        else if (z == 1) { Bgh = B1h; Bgl = B1l; bias = bias1; Ch = C1h; Cl = C1l; mode = 2; }
        else             { Bgh = B2h; Bgl = B2l; bias = bias2; Ch = C2h; Cl = C2l; mode = 3; }
    } else { Bgh = B0h; Bgl = B0l; bias = bias0; mode = 0; }

    float acc[4][4][4];
    #pragma unroll
    for (int i = 0; i < 4; i++)
        #pragma unroll
        for (int j = 0; j < 4; j++)
            #pragma unroll
            for (int r = 0; r < 4; r++) acc[i][j][r] = 0.f;

    // preload stages 0,1
    stage_tiles(sm,               Agh, Agl, Bgh, Bgl, rowBase, colBase, 0, tid);
    asm volatile("cp.async.commit_group;");
    stage_tiles(sm + STAGE_HALFS, Agh, Agl, Bgh, Bgl, rowBase, colBase, 1, tid);
    asm volatile("cp.async.commit_group;");

    const int NIT = D_MODEL / 32;   // 32
    for (int it = 0; it < NIT; it++) {
        asm volatile("cp.async.wait_group 1;");
        __syncthreads();
        __nv_bfloat16* sb = sm + (it & 1) * STAGE_HALFS;
        __nv_bfloat16* sAh = sb;
        __nv_bfloat16* sAl = sb + A_HALFS;
        __nv_bfloat16* sBh = sb + 2 * A_HALFS;
        __nv_bfloat16* sBl = sb + 2 * A_HALFS + B_HALFS;

        #pragma unroll
        for (int ks = 0; ks < 32; ks += 16) {
            uint32_t ah[4][4], al[4][4];
            #pragma unroll
            for (int am = 0; am < 4; am++) {
                int row = wm * 64 + am * 16 + (lane & 15);
                int col = ks + ((lane >> 4) << 3);
                ldm_x4(ah[am], smem_u32(sAh + row * ASTRIDE + col));
                ldm_x4(al[am], smem_u32(sAl + row * ASTRIDE + col));
            }
            #pragma unroll
            for (int an = 0; an < 4; an++) {
                int br = ks + (lane & 15);
                int bc = wn * 32 + an * 8;
                uint32_t bh[2], bl[2];
                ldm_x2_t(bh, smem_u32(sBh + br * BSTRIDE + bc));
                ldm_x2_t(bl, smem_u32(sBl + br * BSTRIDE + bc));
                #pragma unroll
                for (int am = 0; am < 4; am++) {
                    mma_bf16(acc[am][an], ah[am], bh);
                    mma_bf16(acc[am][an], ah[am], bl);
                    mma_bf16(acc[am][an], al[am], bh);
                }
            }
        }
        __syncthreads();
        if (it + 2 < NIT)
            stage_tiles(sm + (it & 1) * STAGE_HALFS, Agh, Agl, Bgh, Bgl,
                        rowBase, colBase, it + 2, tid);
        asm volatile("cp.async.commit_group;");
    }

    // epilogue
    #pragma unroll
    for (int am = 0; am < 4; am++) {
        #pragma unroll
        for (int an = 0; an < 4; an++) {
            int r0 = rowBase + wm * 64 + am * 16 + (lane >> 2);
            int c0 = colBase + wn * 32 + an * 8 + ((lane & 3) << 1);
            float b0 = bias[c0], b1 = bias[c0 + 1];
            float v00 = acc[am][an][0] + b0, v01 = acc[am][an][1] + b1;
            float v10 = acc[am][an][2] + b0, v11 = acc[am][an][3] + b1;
            if (mode == 0) {
                Cf[(size_t)r0 * N + c0]           = v00;
                Cf[(size_t)r0 * N + c0 + 1]       = v01;
                Cf[(size_t)(r0 + 8) * N + c0]     = v10;
                Cf[(size_t)(r0 + 8) * N + c0 + 1] = v11;
            } else {
                if (mode != 3) {
                    int i  = (c0 & 63) >> 1;
                    int s0 = r0 & (SEQ - 1);
                    float2 cs0 = ropeTab[s0 * 32 + i];
                    float2 cs1 = ropeTab[(s0 + 8) * 32 + i];
                    float t;
                    t = v00 * cs0.x - v01 * cs0.y; v01 = v00 * cs0.y + v01 * cs0.x; v00 = t;
                    t = v10 * cs1.x - v11 * cs1.y; v11 = v10 * cs1.y + v11 * cs1.x; v10 = t;
                }
                if (mode == 1) { v00 *= 0.125f; v01 *= 0.125f; v10 *= 0.125f; v11 *= 0.125f; }
                uint32_t h0, l0, h1, l1;
                packsplit(v00, v01, h0, l0);
                packsplit(v10, v11, h1, l1);
                size_t i0 = (size_t)r0 * N + c0;
                size_t i1 = (size_t)(r0 + 8) * N + c0;
                *(uint32_t*)&Ch[i0] = h0; *(uint32_t*)&Cl[i0] = l0;
                *(uint32_t*)&Ch[i1] = h1; *(uint32_t*)&Cl[i1] = l1;
            }
        }
    }
}

// ---------------------------------------------------------------------------
// Tensor-core flash attention (causal). Writes split bf16 output for Wo GEMM.
// Heavy query tiles scheduled first (qt reversed).
// ---------------------------------------------------------------------------
__global__ __launch_bounds__(128) void flash_mma(
    const __nv_bfloat16* __restrict__ Qh, const __nv_bfloat16* __restrict__ Ql,
    const __nv_bfloat16* __restrict__ Kh, const __nv_bfloat16* __restrict__ Kl,
    const __nv_bfloat16* __restrict__ Vh, const __nv_bfloat16* __restrict__ Vl,
    __nv_bfloat16* __restrict__ Oh, __nv_bfloat16* __restrict__ Ol)
{
    __shared__ __align__(16) __nv_bfloat16 sKh[64][72];
    __shared__ __align__(16) __nv_bfloat16 sKl[64][72];
    __shared__ __align__(16) __nv_bfloat16 sVh[64][72];
    __shared__ __align__(16) __nv_bfloat16 sVl[64][72];

    const int tid  = threadIdx.x;
    const int lane = tid & 31;
    const int warp = tid >> 5;
    const int qt = (int)gridDim.x - 1 - (int)blockIdx.x;   // heavy first
    const int bh = blockIdx.y;
    const int b = bh >> 4, h = bh & 15;
    const size_t rowBase = (size_t)b * SEQ;
    const int col0 = h * DK;

    for (int e = tid; e < 512; e += 128) {
        int r = e >> 3, c8 = (e & 7) * 8;
        size_t g = (rowBase + qt * 64 + r) * D_MODEL + col0 + c8;
        *(uint4*)&sKh[r][c8] = *(const uint4*)&Qh[g];
        *(uint4*)&sKl[r][c8] = *(const uint4*)&Ql[g];
    }
    __syncthreads();
    uint32_t qh[4][4], ql[4][4];
    #pragma unroll
    for (int c = 0; c < 4; c++) {
        int row = warp * 16 + (lane & 15);
        int col = c * 16 + ((lane >> 4) << 3);
        ldm_x4(qh[c], smem_u32(&sKh[row][col]));
        ldm_x4(ql[c], smem_u32(&sKl[row][col]));
    }
    __syncthreads();

    float m0 = -1e30f, m1 = -1e30f, l0 = 0.f, l1 = 0.f;
    float o[8][4];
    #pragma unroll
    for (int d = 0; d < 8; d++)
        #pragma unroll
        for (int j = 0; j < 4; j++) o[d][j] = 0.f;

    for (int kt = 0; kt <= qt; kt++) {
        for (int e = tid; e < 512; e += 128) {
            int r = e >> 3, c8 = (e & 7) * 8;
            size_t g = (rowBase + kt * 64 + r) * D_MODEL + col0 + c8;
            *(uint4*)&sKh[r][c8] = *(const uint4*)&Kh[g];
            *(uint4*)&sKl[r][c8] = *(const uint4*)&Kl[g];
            *(uint4*)&sVh[r][c8] = *(const uint4*)&Vh[g];
            *(uint4*)&sVl[r][c8] = *(const uint4*)&Vl[g];
        }
        __syncthreads();

        float s[8][4];
        #pragma unroll
        for (int nt = 0; nt < 8; nt++)
            #pragma unroll
            for (int j = 0; j < 4; j++) s[nt][j] = 0.f;

        #pragma unroll
        for (int ntp = 0; ntp < 4; ntp++) {
            #pragma unroll
            for (int c = 0; c < 4; c++) {
                int row = ntp * 16 + ((lane >> 4) & 1) * 8 + (lane & 7);
                int col = c * 16 + ((lane >> 3) & 1) * 8;
                uint32_t kh4[4], kl4[4];
                ldm_x4(kh4, smem_u32(&sKh[row][col]));
                ldm_x4(kl4, smem_u32(&sKl[row][col]));
                mma_bf16(s[2 * ntp],     qh[c], &kh4[0]);
                mma_bf16(s[2 * ntp],     qh[c], &kl4[0]);
                mma_bf16(s[2 * ntp],     ql[c], &kh4[0]);
                mma_bf16(s[2 * ntp + 1], qh[c], &kh4[2]);
                mma_bf16(s[2 * ntp + 1], qh[c], &kl4[2]);
                mma_bf16(s[2 * ntp + 1], ql[c], &kh4[2]);
            }
        }

        if (kt == qt) {
            int qrow = warp * 16 + (lane >> 2);
            int kcol = (lane & 3) * 2;
            #pragma unroll
            for (int nt = 0; nt < 8; nt++) {
                #pragma unroll
                for (int j = 0; j < 4; j++) {
                    int kpos = nt * 8 + kcol + (j & 1);
                    int qpos = qrow + ((j >> 1) << 3);
                    if (kpos > qpos) s[nt][j] = -1e9f;
                }
            }
        }

        float mx0 = -1e30f, mx1 = -1e30f;
        #pragma unroll
        for (int nt = 0; nt < 8; nt++) {
            mx0 = fmaxf(mx0, fmaxf(s[nt][0], s[nt][1]));
            mx1 = fmaxf(mx1, fmaxf(s[nt][2], s[nt][3]));
        }
        mx0 = fmaxf(mx0, __shfl_xor_sync(0xffffffff, mx0, 1));
        mx0 = fmaxf(mx0, __shfl_xor_sync(0xffffffff, mx0, 2));
        mx1 = fmaxf(mx1, __shfl_xor_sync(0xffffffff, mx1, 1));
        mx1 = fmaxf(mx1, __shfl_xor_sync(0xffffffff, mx1, 2));
        float mn0 = fmaxf(m0, mx0), mn1 = fmaxf(m1, mx1);
        float cr0 = __expf(m0 - mn0), cr1 = __expf(m1 - mn1);
        float sum0 = 0.f, sum1 = 0.f;
        #pragma unroll
        for (int nt = 0; nt < 8; nt++) {
            s[nt][0] = __expf(s[nt][0] - mn0);
            s[nt][1] = __expf(s[nt][1] - mn0);
            s[nt][2] = __expf(s[nt][2] - mn1);
            s[nt][3] = __expf(s[nt][3] - mn1);
            sum0 += s[nt][0] + s[nt][1];
            sum1 += s[nt][2] + s[nt][3];
        }
        sum0 += __shfl_xor_sync(0xffffffff, sum0, 1);
        sum0 += __shfl_xor_sync(0xffffffff, sum0, 2);
        sum1 += __shfl_xor_sync(0xffffffff, sum1, 1);
        sum1 += __shfl_xor_sync(0xffffffff, sum1, 2);
        m0 = mn0; m1 = mn1;
        l0 = l0 * cr0 + sum0;
        l1 = l1 * cr1 + sum1;
        #pragma unroll
        for (int d = 0; d < 8; d++) {
            o[d][0] *= cr0; o[d][1] *= cr0;
            o[d][2] *= cr1; o[d][3] *= cr1;
        }

        uint32_t pah[4][4], pal[4][4];
        #pragma unroll
        for (int c = 0; c < 4; c++) {
            packsplit(s[2*c][0],   s[2*c][1],   pah[c][0], pal[c][0]);
            packsplit(s[2*c][2],   s[2*c][3],   pah[c][1], pal[c][1]);
            packsplit(s[2*c+1][0], s[2*c+1][1], pah[c][2], pal[c][2]);
            packsplit(s[2*c+1][2], s[2*c+1][3], pah[c][3], pal[c][3]);
        }

        #pragma unroll
        for (int dtp = 0; dtp < 4; dtp++) {
            #pragma unroll
            for (int c = 0; c < 4; c++) {
                int row = c * 16 + ((lane >> 3) & 1) * 8 + (lane & 7);
                int col = dtp * 16 + ((lane >> 4) & 1) * 8;
                uint32_t vh4[4], vl4[4];
                ldm_x4_t(vh4, smem_u32(&sVh[row][col]));
                ldm_x4_t(vl4, smem_u32(&sVl[row][col]));
                mma_bf16(o[2 * dtp],     pah[c], &vh4[0]);
                mma_bf16(o[2 * dtp],     pal[c], &vh4[0]);
                mma_bf16(o[2 * dtp],     pah[c], &vl4[0]);
                mma_bf16(o[2 * dtp + 1], pah[c], &vh4[2]);
                mma_bf16(o[2 * dtp + 1], pal[c], &vh4[2]);
                mma_bf16(o[2 * dtp + 1], pah[c], &vl4[2]);
            }
        }
        __syncthreads();
    }

    // finalize: split output to bf16 hi/lo for the Wo GEMM
    float il0 = 1.0f / l0, il1 = 1.0f / l1;
    size_t gr = rowBase + qt * 64 + warp * 16 + (lane >> 2);
    int gc = col0 + (lane & 3) * 2;
    #pragma unroll
    for (int d = 0; d < 8; d++) {
        uint32_t h0, lo0, h1, lo1;
        packsplit(o[d][0] * il0, o[d][1] * il0, h0, lo0);
        packsplit(o[d][2] * il1, o[d][3] * il1, h1, lo1);
        size_t i0 = gr * D_MODEL + gc + d * 8;
        size_t i1 = (gr + 8) * D_MODEL + gc + d * 8;
        *(uint32_t*)&Oh[i0] = h0; *(uint32_t*)&Ol[i0] = lo0;
        *(uint32_t*)&Oh[i1] = h1; *(uint32_t*)&Ol[i1] = lo1;
    }
}

// ---------------------------------------------------------------------------
extern "C" void kernel_launch(void* const* d_in, const int* in_sizes, int n_in,
                              void* d_out, int out_size)
{
    const float* x  = (const float*)d_in[0];
    const float* Wq = (const float*)d_in[1];
    const float* bq = (const float*)d_in[2];
    const float* Wk = (const float*)d_in[3];
    const float* bk = (const float*)d_in[4];
    const float* Wv = (const float*)d_in[5];
    const float* bv = (const float*)d_in[6];
    const float* Wo = (const float*)d_in[7];
    const float* bo = (const float*)d_in[8];
    float* out = (float*)d_out;

    __nv_bfloat16 *xh, *xl, *Wh, *Wl, *Qh, *Ql, *Kh, *Kl, *Vh, *Vl, *Ah, *Al;
    float2* ropeP;
    cudaGetSymbolAddress((void**)&xh, g_xh);  cudaGetSymbolAddress((void**)&xl, g_xl);
    cudaGetSymbolAddress((void**)&Wh, g_Wh);  cudaGetSymbolAddress((void**)&Wl, g_Wl);
    cudaGetSymbolAddress((void**)&Qh, g_Qh);  cudaGetSymbolAddress((void**)&Ql, g_Ql);
    cudaGetSymbolAddress((void**)&Kh, g_Kh);  cudaGetSymbolAddress((void**)&Kl, g_Kl);
    cudaGetSymbolAddress((void**)&Vh, g_Vh);  cudaGetSymbolAddress((void**)&Vl, g_Vl);
    cudaGetSymbolAddress((void**)&Ah, g_Ah);  cudaGetSymbolAddress((void**)&Al, g_Al);
    cudaGetSymbolAddress((void**)&ropeP, g_ropeTab);

    const int WSZ = D_MODEL * D_MODEL;
    __nv_bfloat16 *Wqh = Wh + 0 * WSZ, *Wqh_l = Wl + 0 * WSZ;
    __nv_bfloat16 *Wkh = Wh + 1 * WSZ, *Wkh_l = Wl + 1 * WSZ;
    __nv_bfloat16 *Wvh = Wh + 2 * WSZ, *Wvh_l = Wl + 2 * WSZ;
    __nv_bfloat16 *Woh = Wh + 3 * WSZ, *Woh_l = Wl + 3 * WSZ;

    static int smemSet = 0;
    if (!smemSet) {
        cudaFuncSetAttribute(gemm_pipe, cudaFuncAttributeMaxDynamicSharedMemorySize, SMEM_BYTES);
        smemSet = 1;
    }

    // prep: split inputs once
    split_kernel<<<(MROWS * D_MODEL / 8 + 255) / 256, 256>>>(x, xh, xl, MROWS * D_MODEL / 8);
    split_kernel<<<(WSZ / 8 + 255) / 256, 256>>>(Wq, Wqh, Wqh_l, WSZ / 8);
    split_kernel<<<(WSZ / 8 + 255) / 256, 256>>>(Wk, Wkh, Wkh_l, WSZ / 8);
    split_kernel<<<(WSZ / 8 + 255) / 256, 256>>>(Wv, Wvh, Wvh_l, WSZ / 8);
    split_kernel<<<(WSZ / 8 + 255) / 256, 256>>>(Wo, Woh, Woh_l, WSZ / 8);
    rope_table_kernel<<<SEQ * 32 / 256, 256>>>(ropeP);

    // fused Q/K/V projections (z selects)
    dim3 qkvGrid(D_MODEL / 128, MROWS / 128, 3);   // (8, 32, 3)
    gemm_pipe<<<qkvGrid, 256, SMEM_BYTES>>>(
        xh, xl,
        Wqh, Wqh_l, bq,  Wkh, Wkh_l, bk,  Wvh, Wvh_l, bv,
        Qh, Ql,  Kh, Kl,  Vh, Vl,
        nullptr, ropeP, 1);

    dim3 flashGrid(SEQ / 64, BATCH * NHEAD);       // (32, 32)
    flash_mma<<<flashGrid, 128>>>(Qh, Ql, Kh, Kl, Vh, Vl, Ah, Al);

    // output projection
    dim3 oGrid(D_MODEL / 128, MROWS / 128, 1);
    gemm_pipe<<<oGrid, 256, SMEM_BYTES>>>(
        Ah, Al,
        Woh, Woh_l, bo,  nullptr, nullptr, nullptr,  nullptr, nullptr, nullptr,
        nullptr, nullptr,  nullptr, nullptr,  nullptr, nullptr,
        out, ropeP, 0);
}